// round 4
// baseline (speedup 1.0000x reference)
#include <cuda_runtime.h>
#include <cstdint>
#include <math.h>

// ---------------- scratch (device globals; no allocations allowed) ----------------
__device__ float g_x [26214400];   // 51200 x 512  current node features
__device__ float g_sp[26214400];   // 51200 x 512  spatial output
__device__ float g_u [26214400];   // 51200 x 512  out_node / LN output
__device__ float g_cs[50400];      // 16 x 63 x 50 cos values

#define NEGV (-1.0e9f)

__device__ __forceinline__ float warp_sum(float v) {
#pragma unroll
    for (int o = 16; o; o >>= 1) v += __shfl_xor_sync(0xffffffffu, v, o);
    return v;
}
__device__ __forceinline__ float warp_max(float v) {
#pragma unroll
    for (int o = 16; o; o >>= 1) v = fmaxf(v, __shfl_xor_sync(0xffffffffu, v, o));
    return v;
}

// packed dual-fp32 FMA (SASS FFMA2) — only reachable via explicit PTX
__device__ __forceinline__ void fma2(unsigned long long& d,
                                     unsigned long long a,
                                     unsigned long long b) {
    asm("fma.rn.f32x2 %0, %1, %2, %0;" : "+l"(d) : "l"(a), "l"(b));
}

// ---------------- generic 512-K GEMM: C = epi(A' @ W^T) ----------------
// A' per AMODE: 0 plain A[row]; 1 concat(visual,audio); 2 cos[row]*A[prevRow]; 3 (1-cos[row])*A[curRow]
// EPI: 0: C[row]=acc+bias ; 1: C[orow]=res[orow]+relu(acc+bias) ; 2: C[orow]+=relu(acc+bias) ; 3: C[row]=res[row]+relu(acc)
template<int AMODE, int EPI>
__global__ void __launch_bounds__(256, 2) gemm512(
    const float* __restrict__ A, const float* __restrict__ W,
    const float* __restrict__ bias, float* __restrict__ C, int M,
    const float* __restrict__ cosv, const float* __restrict__ res,
    const float* __restrict__ vis, const float* __restrict__ aud)
{
    // A tile stored DUPLICATED (both halves of each float2 equal) so LDS
    // yields ready-to-use packed operands for fma.rn.f32x2.
    __shared__ float2 As2[16][130];
    __shared__ float  Bs [16][132];
    const int tid = threadIdx.x;
    const int bm = blockIdx.y * 128;
    const int bn = blockIdx.x * 128;
    const int tx = tid & 15, ty = tid >> 4;
    const int tm = ty * 8, tn = tx * 8;

    unsigned long long acc2[8][4];
#pragma unroll
    for (int i = 0; i < 8; i++)
#pragma unroll
        for (int j = 0; j < 4; j++) acc2[i][j] = 0ull;

    for (int kt = 0; kt < 512; kt += 16) {
#pragma unroll
        for (int e = 0; e < 8; e++) {
            int idx = tid + e * 256;
            int k = idx & 15, m = idx >> 4;
            int row = bm + m;
            float v = 0.f;
            if (row < M) {
                int kk = kt + k;
                if (AMODE == 0) {
                    v = A[(size_t)row * 512 + kk];
                } else if (AMODE == 1) {
                    int bt = row / 50; int ii = row - bt * 50;
                    v = (ii < 49) ? vis[((size_t)bt * 49 + ii) * 512 + kk]
                                  : aud[(size_t)bt * 512 + kk];
                } else if (AMODE == 2) {
                    int pr = row + (row / 3150) * 50;
                    v = cosv[row] * A[(size_t)pr * 512 + kk];
                } else {
                    int cr = row + (row / 3150) * 50 + 50;
                    v = (1.f - cosv[row]) * A[(size_t)cr * 512 + kk];
                }
            }
            As2[k][m] = make_float2(v, v);
        }
#pragma unroll
        for (int e = 0; e < 8; e++) {
            int idx = tid + e * 256;
            int k = idx & 15, n = idx >> 4;
            Bs[k][n] = W[(size_t)(bn + n) * 512 + kt + k];
        }
        __syncthreads();
#pragma unroll
        for (int k = 0; k < 16; k++) {
            unsigned long long a2[8], b2[4];
            const ulonglong2* ar = (const ulonglong2*)(&As2[k][tm]);
            ulonglong2 t0 = ar[0], t1 = ar[1], t2 = ar[2], t3 = ar[3];
            a2[0] = t0.x; a2[1] = t0.y; a2[2] = t1.x; a2[3] = t1.y;
            a2[4] = t2.x; a2[5] = t2.y; a2[6] = t3.x; a2[7] = t3.y;
            const ulonglong2* br = (const ulonglong2*)(&Bs[k][tn]);
            ulonglong2 u0 = br[0], u1 = br[1];
            b2[0] = u0.x; b2[1] = u0.y; b2[2] = u1.x; b2[3] = u1.y;
#pragma unroll
            for (int i = 0; i < 8; i++)
#pragma unroll
                for (int j = 0; j < 4; j++) fma2(acc2[i][j], a2[i], b2[j]);
        }
        __syncthreads();
    }

#pragma unroll
    for (int i = 0; i < 8; i++) {
        int row = bm + tm + i;
        if (row >= M) break;
        int orow = row;
        if (EPI == 1 || EPI == 2) orow = row + (row / 3150) * 50 + 50;
#pragma unroll
        for (int j = 0; j < 4; j++) {
            unsigned long long u = acc2[i][j];
            float vlo = __uint_as_float((unsigned)(u & 0xffffffffull));
            float vhi = __uint_as_float((unsigned)(u >> 32));
#pragma unroll
            for (int h = 0; h < 2; h++) {
                int col = bn + tn + 2 * j + h;
                float v = h ? vhi : vlo;
                if (EPI == 0) {
                    C[(size_t)row * 512 + col] = v + bias[col];
                } else if (EPI == 1) {
                    C[(size_t)orow * 512 + col] =
                        res[(size_t)orow * 512 + col] + fmaxf(v + bias[col], 0.f);
                } else if (EPI == 2) {
                    C[(size_t)orow * 512 + col] += fmaxf(v + bias[col], 0.f);
                } else {
                    C[(size_t)row * 512 + col] =
                        res[(size_t)row * 512 + col] + fmaxf(v, 0.f);
                }
            }
        }
    }
}

// ---------------- fused spatial attention per (b,t) tile ----------------
// smem layout (floats): sx[50*516] | se[1536] | ss[50*52] | qn2[50] d0[50] d1[50] d2[50] en2[4] rs[50]
#define SX_STRIDE 516
#define SMEM_SPATIAL_FLOATS (50*516 + 1536 + 50*52 + 50*4 + 4 + 50)
#define SMEM_SPATIAL_BYTES  (SMEM_SPATIAL_FLOATS * 4)

__global__ void spatial_kernel(const float* __restrict__ x,
                               const float* __restrict__ edge,
                               const float* __restrict__ lng,
                               const float* __restrict__ lnb,
                               float* __restrict__ sp,
                               float* __restrict__ attn_out)
{
    extern __shared__ float sm[];
    float* sx  = sm;
    float* se  = sx + 50 * SX_STRIDE;
    float* ss  = se + 1536;
    float* qn2 = ss + 50 * 52;
    float* d0  = qn2 + 50;
    float* d1  = d0 + 50;
    float* d2  = d1 + 50;
    float* en2 = d2 + 50;
    float* rsv = en2 + 4;

    const int bt   = blockIdx.x;
    const int tid  = threadIdx.x;
    const int lane = tid & 31;
    const int w    = tid >> 5;
    const float* xg = x + (size_t)bt * 25600;

    for (int idx = tid; idx < 25600; idx += 256) {
        int i = idx >> 9, k = idx & 511;
        sx[i * SX_STRIDE + k] = xg[idx];
    }
    for (int idx = tid; idx < 1536; idx += 256) se[idx] = edge[idx];
    __syncthreads();

    // edge norms (warps 0..2) + per-row stats (all warps)
    if (w < 3) {
        float s = 0.f;
        for (int k = lane; k < 512; k += 32) { float e = se[w * 512 + k]; s += e * e; }
        s = warp_sum(s);
        if (lane == 0) en2[w] = s;
    }
    for (int i = w; i < 50; i += 8) {
        float sxx = 0.f, s0 = 0.f, s1 = 0.f, s2 = 0.f;
        for (int k = lane; k < 512; k += 32) {
            float v = sx[i * SX_STRIDE + k];
            sxx += v * v;
            s0 += v * se[k];
            s1 += v * se[512 + k];
            s2 += v * se[1024 + k];
        }
        sxx = warp_sum(sxx); s0 = warp_sum(s0); s1 = warp_sum(s1); s2 = warp_sum(s2);
        if (lane == 0) { qn2[i] = sxx; d0[i] = s0; d1[i] = s1; d2[i] = s2; }
    }
    __syncthreads();

    // G = X X^T  (4x4 strided register tile per thread)
    {
        int ty = tid >> 4, tx = tid & 15;
        const float* ap[4]; const float* bp[4];
#pragma unroll
        for (int u = 0; u < 4; u++) {
            int ri = ty + 16 * u; if (ri > 49) ri = 49;
            int rj = tx + 16 * u; if (rj > 49) rj = 49;
            ap[u] = sx + ri * SX_STRIDE;
            bp[u] = sx + rj * SX_STRIDE;
        }
        float acc[4][4];
#pragma unroll
        for (int i = 0; i < 4; i++)
#pragma unroll
            for (int j = 0; j < 4; j++) acc[i][j] = 0.f;
#pragma unroll 4
        for (int k = 0; k < 512; k++) {
            float a[4], b[4];
#pragma unroll
            for (int u = 0; u < 4; u++) { a[u] = ap[u][k]; b[u] = bp[u][k]; }
#pragma unroll
            for (int i = 0; i < 4; i++)
#pragma unroll
                for (int j = 0; j < 4; j++) acc[i][j] += a[i] * b[j];
        }
#pragma unroll
        for (int i = 0; i < 4; i++) {
            int gi = ty + 16 * i; if (gi >= 50) break;
#pragma unroll
            for (int j = 0; j < 4; j++) {
                int gj = tx + 16 * j;
                if (gj < 50) ss[gi * 52 + gj] = acc[i][j];
            }
        }
    }
    __syncthreads();

    // masked softmax per row (warp per row)
    for (int i = w; i < 50; i += 8) {
        float qi = fmaxf(sqrtf(qn2[i]), 1e-12f);
        float sv[2];
#pragma unroll
        for (int c = 0; c < 2; c++) {
            int j = lane + 32 * c;
            float s = -1e30f;
            if (j < 50) {
                if (j == i) {
                    s = NEGV;
                } else if (j == 49) {
                    float kn = fmaxf(sqrtf(qn2[49] + 2.f * d2[49] + en2[2]), 1e-12f);
                    s = (ss[i * 52 + 49] + d2[i]) / (qi * kn);
                } else if (i == 49) {
                    float kn = fmaxf(sqrtf(qn2[j] + 2.f * d1[j] + en2[1]), 1e-12f);
                    s = (ss[i * 52 + j] + d1[49]) / (qi * kn);
                } else {
                    int qr = i / 7, qc = i - qr * 7;
                    int kr = j / 7, kc = j - kr * 7;
                    int r0 = max(qr - 1, 0);
                    int c0 = min(max(qc - 1, 0), 4);
                    bool allow = (kr >= r0) && (kr <= r0 + 2) && (kc >= c0) && (kc <= c0 + 2);
                    if (allow) {
                        float kn = fmaxf(sqrtf(qn2[j] + 2.f * d0[j] + en2[0]), 1e-12f);
                        s = (ss[i * 52 + j] + d0[i]) / (qi * kn);
                    } else {
                        s = NEGV;
                    }
                }
            }
            sv[c] = s;
        }
        float m = warp_max(fmaxf(sv[0], sv[1]));
        float e0v = expf(sv[0] - m);
        float e1v = expf(sv[1] - m);
        if (lane + 32 >= 50) e1v = 0.f;
        float sum = warp_sum(e0v + e1v);
        float p0 = e0v / sum, p1 = e1v / sum;
        float rpart = ((lane < 49) ? p0 : 0.f) + ((lane + 32 < 49) ? p1 : 0.f);
        rpart = warp_sum(rpart);
        if (lane == 0) rsv[i] = rpart;
        if (lane < 50) {
            ss[i * 52 + lane] = p0;
            if (attn_out) attn_out[(size_t)bt * 2500 + i * 50 + lane] = p0;
        }
        if (lane + 32 < 50) {
            ss[i * 52 + lane + 32] = p1;
            if (attn_out) attn_out[(size_t)bt * 2500 + i * 50 + lane + 32] = p1;
        }
    }
    __syncthreads();

    // aggregation (2 rows / warp pass) + residual + LN + relu
    for (int pp = w; pp < 25; pp += 8) {
        int i0 = 2 * pp, i1 = 2 * pp + 1;
        float v0[16], v1[16];
#pragma unroll
        for (int m = 0; m < 16; m++) { v0[m] = 0.f; v1[m] = 0.f; }
        for (int j = 0; j < 50; j++) {
            float a0 = ss[i0 * 52 + j];
            float a1 = ss[i1 * 52 + j];
            const float* xr = sx + j * SX_STRIDE;
#pragma unroll
            for (int m = 0; m < 16; m++) {
                float xv = xr[lane + 32 * m];
                v0[m] += a0 * xv;
                v1[m] += a1 * xv;
            }
        }
#pragma unroll
        for (int which = 0; which < 2; which++) {
            int i = which ? i1 : i0;
            float* v = which ? v1 : v0;
            float rs = rsv[i];
            float a49 = ss[i * 52 + 49];
            const float* esel = (i < 49) ? se : (se + 512);
            float s = 0.f, s2 = 0.f;
#pragma unroll
            for (int m = 0; m < 16; m++) {
                int h = lane + 32 * m;
                float t = v[m] + rs * esel[h] + a49 * se[1024 + h] + sx[i * SX_STRIDE + h];
                v[m] = t;
                s += t; s2 += t * t;
            }
            s = warp_sum(s); s2 = warp_sum(s2);
            float mean = s * (1.f / 512.f);
            float var = s2 * (1.f / 512.f) - mean * mean;
            float rstd = rsqrtf(var + 1e-5f);
#pragma unroll
            for (int m = 0; m < 16; m++) {
                int h = lane + 32 * m;
                float y = (v[m] - mean) * rstd * lng[h] + lnb[h];
                sp[(size_t)bt * 25600 + i * 512 + h] = fmaxf(y, 0.f);
            }
        }
    }
}

// ---------------- temporal cosine ----------------
__global__ void cos_kernel(const float* __restrict__ sp, float* __restrict__ cosv,
                           float* __restrict__ cos_out)
{
    int r = blockIdx.x * 8 + (threadIdx.x >> 5);
    if (r >= 50400) return;
    int lane = threadIdx.x & 31;
    int b = r / 3150, rem = r - b * 3150;
    int tm = rem / 50, i = rem - tm * 50;
    const float* pa = sp + (size_t)((b * 64 + tm + 1) * 50 + i) * 512;
    const float* pb = sp + (size_t)((b * 64 + tm) * 50 + i) * 512;
    float dt = 0.f, na = 0.f, nb = 0.f;
    for (int k = lane; k < 512; k += 32) {
        float av = pa[k], bv = pb[k];
        dt += av * bv; na += av * av; nb += bv * bv;
    }
    dt = warp_sum(dt); na = warp_sum(na); nb = warp_sum(nb);
    if (lane == 0) {
        float c = dt / (fmaxf(sqrtf(na), 1e-8f) * fmaxf(sqrtf(nb), 1e-8f));
        cosv[r] = c;
        if (cos_out) cos_out[r] = c;
    }
}

// ---------------- layernorm of out_node (t==0 rows come from spatial) ----------------
__global__ void ln_kernel(const float* __restrict__ sp, const float* __restrict__ u,
                          const float* __restrict__ g, const float* __restrict__ b,
                          float* __restrict__ y)
{
    int r = blockIdx.x * 8 + (threadIdx.x >> 5);
    if (r >= 51200) return;
    int lane = threadIdx.x & 31;
    int t = (r / 50) & 63;
    const float* src = (t == 0) ? (sp + (size_t)r * 512) : (u + (size_t)r * 512);
    float v[16];
    float s = 0.f, s2 = 0.f;
#pragma unroll
    for (int m = 0; m < 16; m++) {
        float xv = src[lane + 32 * m];
        v[m] = xv; s += xv; s2 += xv * xv;
    }
    s = warp_sum(s); s2 = warp_sum(s2);
    float mean = s * (1.f / 512.f);
    float var = s2 * (1.f / 512.f) - mean * mean;
    float rstd = rsqrtf(var + 1e-5f);
#pragma unroll
    for (int m = 0; m < 16; m++) {
        int h = lane + 32 * m;
        y[(size_t)r * 512 + h] = (v[m] - mean) * rstd * g[h] + b[h];
    }
}

// ---------------- launch ----------------
extern "C" void kernel_launch(void* const* d_in, const int* in_sizes, int n_in,
                              void* d_out, int out_size)
{
    const float* vis   = (const float*)d_in[0];
    const float* aud   = (const float*)d_in[1];
    const float* in_W  = (const float*)d_in[2];
    const float* in_b  = (const float*)d_in[3];
    const float* out_W = (const float*)d_in[4];
    const float* out_b = (const float*)d_in[5];
    const float* L[2][8];
    for (int l = 0; l < 2; l++)
        for (int p = 0; p < 8; p++)
            L[l][p] = (const float*)d_in[6 + l * 8 + p];
    // per layer: 0 edge, 1 ln_g, 2 ln_b, 3 Wc, 4 bc, 5 Ws, 6 bs, 7 Wo

    float *px, *psp, *pu, *pcos;
    cudaGetSymbolAddress((void**)&px,   g_x);
    cudaGetSymbolAddress((void**)&psp,  g_sp);
    cudaGetSymbolAddress((void**)&pu,   g_u);
    cudaGetSymbolAddress((void**)&pcos, g_cs);

    float* out      = (float*)d_out;
    float* attn_out = out + 26214400;     // [16,64,50,50]
    float* cos_out  = out + 26214400 + 2560000;  // [16,63,50,1]

    cudaFuncSetAttribute(spatial_kernel,
                         cudaFuncAttributeMaxDynamicSharedMemorySize,
                         SMEM_SPATIAL_BYTES);

    dim3 g400(4, 400), g394(4, 394);

    // input projection: node = concat(visual, audio) @ in_W^T + in_b
    gemm512<1, 0><<<g400, 256>>>(nullptr, in_W, in_b, px, 51200,
                                 nullptr, nullptr, vis, aud);

    for (int l = 0; l < 2; l++) {
        bool last = (l == 1);
        spatial_kernel<<<1024, 256, SMEM_SPATIAL_BYTES>>>(
            px, L[l][0], L[l][1], L[l][2], psp, last ? attn_out : nullptr);
        cos_kernel<<<6300, 256>>>(psp, pcos, last ? cos_out : nullptr);
        // tc: g_u[cur] = cur + relu((cos*prev) @ Wc^T + bc)
        gemm512<2, 1><<<g394, 256>>>(psp, L[l][3], L[l][4], pu, 50400,
                                     pcos, psp, nullptr, nullptr);
        // ts: g_u[cur] += relu((cur*(1-cos)) @ Ws^T + bs)
        gemm512<3, 2><<<g394, 256>>>(psp, L[l][5], L[l][6], pu, 50400,
                                     pcos, nullptr, nullptr, nullptr);
        // layernorm(out_node) -> g_u (t==0 rows sourced from spatial)
        ln_kernel<<<6400, 256>>>(psp, pu, L[l][1], L[l][2], pu);
        // node = node + relu(LN @ Wo^T)   (in-place residual on g_x)
        gemm512<0, 3><<<g400, 256>>>(pu, L[l][7], nullptr, px, 51200,
                                     nullptr, px, nullptr, nullptr);
    }

    // final projection -> out
    gemm512<0, 0><<<g400, 256>>>(px, out_W, out_b, out, 51200,
                                 nullptr, nullptr, nullptr, nullptr);
}

// round 9
// speedup vs baseline: 1.2147x; 1.2147x over previous
#include <cuda_runtime.h>
#include <cstdint>
#include <math.h>

// ---------------- scratch (device globals; no allocations allowed) ----------------
__device__ float g_x [26214400];   // 51200 x 512  current node features
__device__ float g_sp[26214400];   // 51200 x 512  spatial output
__device__ float g_u [26214400];   // 51200 x 512  out_node / LN output
__device__ float g_cs[50400];      // 16 x 63 x 50 cos values

#define NEGV (-1.0e9f)

__device__ __forceinline__ float warp_sum(float v) {
#pragma unroll
    for (int o = 16; o; o >>= 1) v += __shfl_xor_sync(0xffffffffu, v, o);
    return v;
}
__device__ __forceinline__ float warp_max(float v) {
#pragma unroll
    for (int o = 16; o; o >>= 1) v = fmaxf(v, __shfl_xor_sync(0xffffffffu, v, o));
    return v;
}

// packed dual-fp32 FMA (SASS FFMA2) — only reachable via explicit PTX
__device__ __forceinline__ void fma2(unsigned long long& d,
                                     unsigned long long a,
                                     unsigned long long b) {
    asm("fma.rn.f32x2 %0, %1, %2, %0;" : "+l"(d) : "l"(a), "l"(b));
}
// duplicate one fp32 into both halves of a packed u64 (single MOV pair)
__device__ __forceinline__ unsigned long long dup2(float v) {
    unsigned long long r;
    asm("mov.b64 %0, {%1, %1};" : "=l"(r) : "f"(v));
    return r;
}

// ---------------- generic 512-K GEMM: C = epi(A' @ W^T) ----------------
// A' per AMODE: 0 plain A[row]; 1 concat(visual,audio); 2 cos[row]*A[prevRow]; 3 (1-cos[row])*A[curRow]
// EPI: 0: C[row]=acc+bias ; 1: C[orow]=res[orow]+relu(acc+bias) ; 2: C[orow]+=relu(acc+bias) ; 3: C[row]=res[row]+relu(acc)
template<int AMODE, int EPI>
__global__ void __launch_bounds__(256, 2) gemm512(
    const float* __restrict__ A, const float* __restrict__ W,
    const float* __restrict__ bias, float* __restrict__ C, int M,
    const float* __restrict__ cosv, const float* __restrict__ res,
    const float* __restrict__ vis, const float* __restrict__ aud)
{
    // natural (un-duplicated) tiles, double-buffered
    __shared__ float As[2][16][132];
    __shared__ float Bs[2][16][132];
    const int tid = threadIdx.x;
    const int bm = blockIdx.y * 128;
    const int bn = blockIdx.x * 128;
    const int tx = tid & 15, ty = tid >> 4;
    const int tm = ty * 8, tn = tx * 8;
    const int lk = tid & 15, lm = tid >> 4;   // element-load coords

    // acc2[ip][j]: packed rows (tm+2*ip, tm+2*ip+1), col tn+j
    unsigned long long acc2[4][8];
#pragma unroll
    for (int i = 0; i < 4; i++)
#pragma unroll
        for (int j = 0; j < 8; j++) acc2[i][j] = 0ull;

    float ra[8], rb[8];

    // ---- tile loaders (global -> regs) ----
    auto loadA = [&](int kt, float* r) {
#pragma unroll
        for (int e = 0; e < 8; e++) {
            int m = lm + e * 16;          // 16 rows per pass
            int row = bm + m;
            float v = 0.f;
            if (row < M) {
                int kk = kt + lk;
                if (AMODE == 0) {
                    v = A[(size_t)row * 512 + kk];
                } else if (AMODE == 1) {
                    int bt = row / 50; int ii = row - bt * 50;
                    v = (ii < 49) ? vis[((size_t)bt * 49 + ii) * 512 + kk]
                                  : aud[(size_t)bt * 512 + kk];
                } else if (AMODE == 2) {
                    int pr = row + (row / 3150) * 50;
                    v = cosv[row] * A[(size_t)pr * 512 + kk];
                } else {
                    int cr = row + (row / 3150) * 50 + 50;
                    v = (1.f - cosv[row]) * A[(size_t)cr * 512 + kk];
                }
            }
            r[e] = v;
        }
    };
    auto loadB = [&](int kt, float* r) {
#pragma unroll
        for (int e = 0; e < 8; e++) {
            int n = lm + e * 16;
            r[e] = W[(size_t)(bn + n) * 512 + kt + lk];
        }
    };
    auto stsTile = [&](int buf, const float* a, const float* b) {
#pragma unroll
        for (int e = 0; e < 8; e++) {
            As[buf][lk][lm + e * 16] = a[e];
            Bs[buf][lk][lm + e * 16] = b[e];
        }
    };

    // prologue
    loadA(0, ra); loadB(0, rb);
    stsTile(0, ra, rb);
    __syncthreads();

    for (int kt = 0; kt < 32; kt++) {
        const int buf = kt & 1;
        if (kt < 31) { loadA((kt + 1) * 16, ra); loadB((kt + 1) * 16, rb); }
#pragma unroll
        for (int k = 0; k < 16; k++) {
            // A: 8 consecutive rows -> 4 naturally packed pairs
            ulonglong2 av0 = *(const ulonglong2*)&As[buf][k][tm];
            ulonglong2 av1 = *(const ulonglong2*)&As[buf][k][tm + 4];
            unsigned long long a2[4] = {av0.x, av0.y, av1.x, av1.y};
            // B: 8 scalars, duplicated into packed operands in registers
            float4 b0 = *(const float4*)&Bs[buf][k][tn];
            float4 b1 = *(const float4*)&Bs[buf][k][tn + 4];
            unsigned long long b2[8];
            b2[0] = dup2(b0.x); b2[1] = dup2(b0.y);
            b2[2] = dup2(b0.z); b2[3] = dup2(b0.w);
            b2[4] = dup2(b1.x); b2[5] = dup2(b1.y);
            b2[6] = dup2(b1.z); b2[7] = dup2(b1.w);
#pragma unroll
            for (int i = 0; i < 4; i++)
#pragma unroll
                for (int j = 0; j < 8; j++) fma2(acc2[i][j], a2[i], b2[j]);
        }
        if (kt < 31) {
            stsTile(buf ^ 1, ra, rb);
            __syncthreads();
        }
    }

#pragma unroll
    for (int ip = 0; ip < 4; ip++) {
#pragma unroll
        for (int h = 0; h < 2; h++) {
            int row = bm + tm + 2 * ip + h;
            if (row >= M) continue;
            int orow = row;
            if (EPI == 1 || EPI == 2) orow = row + (row / 3150) * 50 + 50;
#pragma unroll
            for (int j = 0; j < 8; j++) {
                unsigned long long u = acc2[ip][j];
                float v = h ? __uint_as_float((unsigned)(u >> 32))
                            : __uint_as_float((unsigned)(u & 0xffffffffull));
                int col = bn + tn + j;
                if (EPI == 0) {
                    C[(size_t)row * 512 + col] = v + bias[col];
                } else if (EPI == 1) {
                    C[(size_t)orow * 512 + col] =
                        res[(size_t)orow * 512 + col] + fmaxf(v + bias[col], 0.f);
                } else if (EPI == 2) {
                    C[(size_t)orow * 512 + col] += fmaxf(v + bias[col], 0.f);
                } else {
                    C[(size_t)row * 512 + col] =
                        res[(size_t)row * 512 + col] + fmaxf(v, 0.f);
                }
            }
        }
    }
}

// ---------------- fused spatial attention per (b,t) tile ----------------
// smem layout (floats): sx[50*516] | se[1536] | ss[50*52] | qn2[50] d0[50] d1[50] d2[50] en2[4] rs[50]
#define SX_STRIDE 516
#define SMEM_SPATIAL_FLOATS (50*516 + 1536 + 50*52 + 50*4 + 4 + 50)
#define SMEM_SPATIAL_BYTES  (SMEM_SPATIAL_FLOATS * 4)

__global__ void spatial_kernel(const float* __restrict__ x,
                               const float* __restrict__ edge,
                               const float* __restrict__ lng,
                               const float* __restrict__ lnb,
                               float* __restrict__ sp,
                               float* __restrict__ attn_out)
{
    extern __shared__ float sm[];
    float* sx  = sm;
    float* se  = sx + 50 * SX_STRIDE;
    float* ss  = se + 1536;
    float* qn2 = ss + 50 * 52;
    float* d0  = qn2 + 50;
    float* d1  = d0 + 50;
    float* d2  = d1 + 50;
    float* en2 = d2 + 50;
    float* rsv = en2 + 4;

    const int bt   = blockIdx.x;
    const int tid  = threadIdx.x;
    const int lane = tid & 31;
    const int w    = tid >> 5;
    const float* xg = x + (size_t)bt * 25600;

    for (int idx = tid; idx < 25600; idx += 256) {
        int i = idx >> 9, k = idx & 511;
        sx[i * SX_STRIDE + k] = xg[idx];
    }
    for (int idx = tid; idx < 1536; idx += 256) se[idx] = edge[idx];
    __syncthreads();

    // edge norms (warps 0..2) + per-row stats (all warps)
    if (w < 3) {
        float s = 0.f;
        for (int k = lane; k < 512; k += 32) { float e = se[w * 512 + k]; s += e * e; }
        s = warp_sum(s);
        if (lane == 0) en2[w] = s;
    }
    for (int i = w; i < 50; i += 8) {
        float sxx = 0.f, s0 = 0.f, s1 = 0.f, s2 = 0.f;
        for (int k = lane; k < 512; k += 32) {
            float v = sx[i * SX_STRIDE + k];
            sxx += v * v;
            s0 += v * se[k];
            s1 += v * se[512 + k];
            s2 += v * se[1024 + k];
        }
        sxx = warp_sum(sxx); s0 = warp_sum(s0); s1 = warp_sum(s1); s2 = warp_sum(s2);
        if (lane == 0) { qn2[i] = sxx; d0[i] = s0; d1[i] = s1; d2[i] = s2; }
    }
    __syncthreads();

    // G = X X^T  (4x4 strided register tile per thread)
    {
        int ty = tid >> 4, tx = tid & 15;
        const float* ap[4]; const float* bp[4];
#pragma unroll
        for (int u = 0; u < 4; u++) {
            int ri = ty + 16 * u; if (ri > 49) ri = 49;
            int rj = tx + 16 * u; if (rj > 49) rj = 49;
            ap[u] = sx + ri * SX_STRIDE;
            bp[u] = sx + rj * SX_STRIDE;
        }
        float acc[4][4];
#pragma unroll
        for (int i = 0; i < 4; i++)
#pragma unroll
            for (int j = 0; j < 4; j++) acc[i][j] = 0.f;
#pragma unroll 4
        for (int k = 0; k < 512; k++) {
            float a[4], b[4];
#pragma unroll
            for (int u = 0; u < 4; u++) { a[u] = ap[u][k]; b[u] = bp[u][k]; }
#pragma unroll
            for (int i = 0; i < 4; i++)
#pragma unroll
                for (int j = 0; j < 4; j++) acc[i][j] += a[i] * b[j];
        }
#pragma unroll
        for (int i = 0; i < 4; i++) {
            int gi = ty + 16 * i; if (gi >= 50) break;
#pragma unroll
            for (int j = 0; j < 4; j++) {
                int gj = tx + 16 * j;
                if (gj < 50) ss[gi * 52 + gj] = acc[i][j];
            }
        }
    }
    __syncthreads();

    // masked softmax per row (warp per row)
    for (int i = w; i < 50; i += 8) {
        float qi = fmaxf(sqrtf(qn2[i]), 1e-12f);
        float sv[2];
#pragma unroll
        for (int c = 0; c < 2; c++) {
            int j = lane + 32 * c;
            float s = -1e30f;
            if (j < 50) {
                if (j == i) {
                    s = NEGV;
                } else if (j == 49) {
                    float kn = fmaxf(sqrtf(qn2[49] + 2.f * d2[49] + en2[2]), 1e-12f);
                    s = (ss[i * 52 + 49] + d2[i]) / (qi * kn);
                } else if (i == 49) {
                    float kn = fmaxf(sqrtf(qn2[j] + 2.f * d1[j] + en2[1]), 1e-12f);
                    s = (ss[i * 52 + j] + d1[49]) / (qi * kn);
                } else {
                    int qr = i / 7, qc = i - qr * 7;
                    int kr = j / 7, kc = j - kr * 7;
                    int r0 = max(qr - 1, 0);
                    int c0 = min(max(qc - 1, 0), 4);
                    bool allow = (kr >= r0) && (kr <= r0 + 2) && (kc >= c0) && (kc <= c0 + 2);
                    if (allow) {
                        float kn = fmaxf(sqrtf(qn2[j] + 2.f * d0[j] + en2[0]), 1e-12f);
                        s = (ss[i * 52 + j] + d0[i]) / (qi * kn);
                    } else {
                        s = NEGV;
                    }
                }
            }
            sv[c] = s;
        }
        float m = warp_max(fmaxf(sv[0], sv[1]));
        float e0v = expf(sv[0] - m);
        float e1v = expf(sv[1] - m);
        if (lane + 32 >= 50) e1v = 0.f;
        float sum = warp_sum(e0v + e1v);
        float p0 = e0v / sum, p1 = e1v / sum;
        float rpart = ((lane < 49) ? p0 : 0.f) + ((lane + 32 < 49) ? p1 : 0.f);
        rpart = warp_sum(rpart);
        if (lane == 0) rsv[i] = rpart;
        if (lane < 50) {
            ss[i * 52 + lane] = p0;
            if (attn_out) attn_out[(size_t)bt * 2500 + i * 50 + lane] = p0;
        }
        if (lane + 32 < 50) {
            ss[i * 52 + lane + 32] = p1;
            if (attn_out) attn_out[(size_t)bt * 2500 + i * 50 + lane + 32] = p1;
        }
    }
    __syncthreads();

    // aggregation (2 rows / warp pass) + residual + LN + relu
    for (int pp = w; pp < 25; pp += 8) {
        int i0 = 2 * pp, i1 = 2 * pp + 1;
        float v0[16], v1[16];
#pragma unroll
        for (int m = 0; m < 16; m++) { v0[m] = 0.f; v1[m] = 0.f; }
        for (int j = 0; j < 50; j++) {
            float a0 = ss[i0 * 52 + j];
            float a1 = ss[i1 * 52 + j];
            const float* xr = sx + j * SX_STRIDE;
#pragma unroll
            for (int m = 0; m < 16; m++) {
                float xv = xr[lane + 32 * m];
                v0[m] += a0 * xv;
                v1[m] += a1 * xv;
            }
        }
#pragma unroll
        for (int which = 0; which < 2; which++) {
            int i = which ? i1 : i0;
            float* v = which ? v1 : v0;
            float rs = rsv[i];
            float a49 = ss[i * 52 + 49];
            const float* esel = (i < 49) ? se : (se + 512);
            float s = 0.f, s2 = 0.f;
#pragma unroll
            for (int m = 0; m < 16; m++) {
                int h = lane + 32 * m;
                float t = v[m] + rs * esel[h] + a49 * se[1024 + h] + sx[i * SX_STRIDE + h];
                v[m] = t;
                s += t; s2 += t * t;
            }
            s = warp_sum(s); s2 = warp_sum(s2);
            float mean = s * (1.f / 512.f);
            float var = s2 * (1.f / 512.f) - mean * mean;
            float rstd = rsqrtf(var + 1e-5f);
#pragma unroll
            for (int m = 0; m < 16; m++) {
                int h = lane + 32 * m;
                float y = (v[m] - mean) * rstd * lng[h] + lnb[h];
                sp[(size_t)bt * 25600 + i * 512 + h] = fmaxf(y, 0.f);
            }
        }
    }
}

// ---------------- temporal cosine ----------------
__global__ void cos_kernel(const float* __restrict__ sp, float* __restrict__ cosv,
                           float* __restrict__ cos_out)
{
    int r = blockIdx.x * 8 + (threadIdx.x >> 5);
    if (r >= 50400) return;
    int lane = threadIdx.x & 31;
    int b = r / 3150, rem = r - b * 3150;
    int tm = rem / 50, i = rem - tm * 50;
    const float* pa = sp + (size_t)((b * 64 + tm + 1) * 50 + i) * 512;
    const float* pb = sp + (size_t)((b * 64 + tm) * 50 + i) * 512;
    float dt = 0.f, na = 0.f, nb = 0.f;
    for (int k = lane; k < 512; k += 32) {
        float av = pa[k], bv = pb[k];
        dt += av * bv; na += av * av; nb += bv * bv;
    }
    dt = warp_sum(dt); na = warp_sum(na); nb = warp_sum(nb);
    if (lane == 0) {
        float c = dt / (fmaxf(sqrtf(na), 1e-8f) * fmaxf(sqrtf(nb), 1e-8f));
        cosv[r] = c;
        if (cos_out) cos_out[r] = c;
    }
}

// ---------------- layernorm of out_node (t==0 rows come from spatial) ----------------
__global__ void ln_kernel(const float* __restrict__ sp, const float* __restrict__ u,
                          const float* __restrict__ g, const float* __restrict__ b,
                          float* __restrict__ y)
{
    int r = blockIdx.x * 8 + (threadIdx.x >> 5);
    if (r >= 51200) return;
    int lane = threadIdx.x & 31;
    int t = (r / 50) & 63;
    const float* src = (t == 0) ? (sp + (size_t)r * 512) : (u + (size_t)r * 512);
    float v[16];
    float s = 0.f, s2 = 0.f;
#pragma unroll
    for (int m = 0; m < 16; m++) {
        float xv = src[lane + 32 * m];
        v[m] = xv; s += xv; s2 += xv * xv;
    }
    s = warp_sum(s); s2 = warp_sum(s2);
    float mean = s * (1.f / 512.f);
    float var = s2 * (1.f / 512.f) - mean * mean;
    float rstd = rsqrtf(var + 1e-5f);
#pragma unroll
    for (int m = 0; m < 16; m++) {
        int h = lane + 32 * m;
        y[(size_t)r * 512 + h] = (v[m] - mean) * rstd * g[h] + b[h];
    }
}

// ---------------- launch ----------------
extern "C" void kernel_launch(void* const* d_in, const int* in_sizes, int n_in,
                              void* d_out, int out_size)
{
    const float* vis   = (const float*)d_in[0];
    const float* aud   = (const float*)d_in[1];
    const float* in_W  = (const float*)d_in[2];
    const float* in_b  = (const float*)d_in[3];
    const float* out_W = (const float*)d_in[4];
    const float* out_b = (const float*)d_in[5];
    const float* L[2][8];
    for (int l = 0; l < 2; l++)
        for (int p = 0; p < 8; p++)
            L[l][p] = (const float*)d_in[6 + l * 8 + p];
    // per layer: 0 edge, 1 ln_g, 2 ln_b, 3 Wc, 4 bc, 5 Ws, 6 bs, 7 Wo

    float *px, *psp, *pu, *pcos;
    cudaGetSymbolAddress((void**)&px,   g_x);
    cudaGetSymbolAddress((void**)&psp,  g_sp);
    cudaGetSymbolAddress((void**)&pu,   g_u);
    cudaGetSymbolAddress((void**)&pcos, g_cs);

    float* out      = (float*)d_out;
    float* attn_out = out + 26214400;     // [16,64,50,50]
    float* cos_out  = out + 26214400 + 2560000;  // [16,63,50,1]

    cudaFuncSetAttribute(spatial_kernel,
                         cudaFuncAttributeMaxDynamicSharedMemorySize,
                         SMEM_SPATIAL_BYTES);

    dim3 g400(4, 400), g394(4, 394);

    // input projection: node = concat(visual, audio) @ in_W^T + in_b
    gemm512<1, 0><<<g400, 256>>>(nullptr, in_W, in_b, px, 51200,
                                 nullptr, nullptr, vis, aud);

    for (int l = 0; l < 2; l++) {
        bool last = (l == 1);
        spatial_kernel<<<1024, 256, SMEM_SPATIAL_BYTES>>>(
            px, L[l][0], L[l][1], L[l][2], psp, last ? attn_out : nullptr);
        cos_kernel<<<6300, 256>>>(psp, pcos, last ? cos_out : nullptr);
        // tc: g_u[cur] = cur + relu((cos*prev) @ Wc^T + bc)
        gemm512<2, 1><<<g394, 256>>>(psp, L[l][3], L[l][4], pu, 50400,
                                     pcos, psp, nullptr, nullptr);
        // ts: g_u[cur] += relu((cur*(1-cos)) @ Ws^T + bs)
        gemm512<3, 2><<<g394, 256>>>(psp, L[l][5], L[l][6], pu, 50400,
                                     pcos, nullptr, nullptr, nullptr);
        // layernorm(out_node) -> g_u (t==0 rows sourced from spatial)
        ln_kernel<<<6400, 256>>>(psp, pu, L[l][1], L[l][2], pu);
        // node = node + relu(LN @ Wo^T)   (in-place residual on g_x)
        gemm512<0, 3><<<g400, 256>>>(pu, L[l][7], nullptr, px, 51200,
                                     nullptr, px, nullptr, nullptr);
    }

    // final projection -> out
    gemm512<0, 0><<<g400, 256>>>(px, out_W, out_b, out, 51200,
                                 nullptr, nullptr, nullptr, nullptr);
}

// round 14
// speedup vs baseline: 1.3761x; 1.1328x over previous
#include <cuda_runtime.h>
#include <cstdint>
#include <math.h>

// ---------------- scratch (device globals; no allocations allowed) ----------------
__device__ float g_x [26214400];   // 51200 x 512  current node features
__device__ float g_sp[26214400];   // 51200 x 512  spatial output
__device__ float g_u [26214400];   // 51200 x 512  out_node / LN output
__device__ float g_cs[50400];      // 16 x 63 x 50 cos values

#define NEGV (-1.0e9f)

__device__ __forceinline__ float warp_sum(float v) {
#pragma unroll
    for (int o = 16; o; o >>= 1) v += __shfl_xor_sync(0xffffffffu, v, o);
    return v;
}
__device__ __forceinline__ float warp_max(float v) {
#pragma unroll
    for (int o = 16; o; o >>= 1) v = fmaxf(v, __shfl_xor_sync(0xffffffffu, v, o));
    return v;
}

// packed dual-fp32 FMA (SASS FFMA2) — only reachable via explicit PTX
__device__ __forceinline__ void fma2(unsigned long long& d,
                                     unsigned long long a,
                                     unsigned long long b) {
    asm("fma.rn.f32x2 %0, %1, %2, %0;" : "+l"(d) : "l"(a), "l"(b));
}
// duplicate one fp32 into both halves of a packed u64 (single MOV pair)
__device__ __forceinline__ unsigned long long dup2(float v) {
    unsigned long long r;
    asm("mov.b64 %0, {%1, %1};" : "=l"(r) : "f"(v));
    return r;
}

// ---------------- generic 512-K GEMM: C = epi(A' @ W^T) ----------------
// A' per AMODE: 0 plain A[row]; 1 concat(visual,audio); 2 cos[row]*A[prevRow]; 3 (1-cos[row])*A[curRow]
// EPI: 0: C[row]=acc+bias ; 1: C[orow]=res[orow]+relu(acc+bias) ; 2: C[orow]+=relu(acc+bias) ; 3: C[row]=res[row]+relu(acc)
template<int AMODE, int EPI>
__global__ void __launch_bounds__(256, 2) gemm512(
    const float* __restrict__ A, const float* __restrict__ W,
    const float* __restrict__ bias, float* __restrict__ C, int M,
    const float* __restrict__ cosv, const float* __restrict__ res,
    const float* __restrict__ vis, const float* __restrict__ aud)
{
    // natural (un-duplicated) tiles, double-buffered
    __shared__ float As[2][16][132];
    __shared__ float Bs[2][16][132];
    const int tid = threadIdx.x;
    const int bm = blockIdx.y * 128;
    const int bn = blockIdx.x * 128;
    const int lane = tid & 31;
    const int w    = tid >> 5;
    // warp spans 4 ty x 8 tx -> contiguous LDS footprints (min wavefronts)
    const int ty = (w & 3) * 4 + (lane >> 3);   // 0..15
    const int tx = (w >> 2) * 8 + (lane & 7);   // 0..15
    const int tm0 = ty * 4, tm1 = ty * 4 + 64;  // two 4-row chunks
    const int tn0 = tx * 4, tn1 = tx * 4 + 64;  // two 4-col chunks
    const int lk = tid & 15, lm = tid >> 4;     // element-load coords

    // acc2[rp][j]: rp 0,1 = row pairs in chunk0; rp 2,3 = row pairs in chunk1.
    // j 0..3 = cols tn0+j ; j 4..7 = cols tn1+(j-4)
    unsigned long long acc2[4][8];
#pragma unroll
    for (int i = 0; i < 4; i++)
#pragma unroll
        for (int j = 0; j < 8; j++) acc2[i][j] = 0ull;

    float ra[8], rb[8];

    // ---- tile loaders (global -> regs) ----
    auto loadA = [&](int kt, float* r) {
#pragma unroll
        for (int e = 0; e < 8; e++) {
            int m = lm + e * 16;          // 16 rows per pass
            int row = bm + m;
            float v = 0.f;
            if (row < M) {
                int kk = kt + lk;
                if (AMODE == 0) {
                    v = A[(size_t)row * 512 + kk];
                } else if (AMODE == 1) {
                    int bt = row / 50; int ii = row - bt * 50;
                    v = (ii < 49) ? vis[((size_t)bt * 49 + ii) * 512 + kk]
                                  : aud[(size_t)bt * 512 + kk];
                } else if (AMODE == 2) {
                    int pr = row + (row / 3150) * 50;
                    v = cosv[row] * A[(size_t)pr * 512 + kk];
                } else {
                    int cr = row + (row / 3150) * 50 + 50;
                    v = (1.f - cosv[row]) * A[(size_t)cr * 512 + kk];
                }
            }
            r[e] = v;
        }
    };
    auto loadB = [&](int kt, float* r) {
#pragma unroll
        for (int e = 0; e < 8; e++) {
            int n = lm + e * 16;
            r[e] = W[(size_t)(bn + n) * 512 + kt + lk];
        }
    };
    auto stsTile = [&](int buf, const float* a, const float* b) {
#pragma unroll
        for (int e = 0; e < 8; e++) {
            As[buf][lk][lm + e * 16] = a[e];
            Bs[buf][lk][lm + e * 16] = b[e];
        }
    };

    // prologue
    loadA(0, ra); loadB(0, rb);
    stsTile(0, ra, rb);
    __syncthreads();

    for (int kt = 0; kt < 32; kt++) {
        const int buf = kt & 1;
        if (kt < 31) { loadA((kt + 1) * 16, ra); loadB((kt + 1) * 16, rb); }
#pragma unroll
        for (int k = 0; k < 16; k++) {
            // A: two 4-row contiguous chunks -> 4 naturally packed pairs
            ulonglong2 av0 = *(const ulonglong2*)&As[buf][k][tm0];
            ulonglong2 av1 = *(const ulonglong2*)&As[buf][k][tm1];
            unsigned long long a2[4] = {av0.x, av0.y, av1.x, av1.y};
            // B: two 4-col contiguous chunks, duplicated into packed operands
            float4 b0 = *(const float4*)&Bs[buf][k][tn0];
            float4 b1 = *(const float4*)&Bs[buf][k][tn1];
            unsigned long long b2[8];
            b2[0] = dup2(b0.x); b2[1] = dup2(b0.y);
            b2[2] = dup2(b0.z); b2[3] = dup2(b0.w);
            b2[4] = dup2(b1.x); b2[5] = dup2(b1.y);
            b2[6] = dup2(b1.z); b2[7] = dup2(b1.w);
#pragma unroll
            for (int i = 0; i < 4; i++)
#pragma unroll
                for (int j = 0; j < 8; j++) fma2(acc2[i][j], a2[i], b2[j]);
        }
        if (kt < 31) {
            stsTile(buf ^ 1, ra, rb);
            __syncthreads();
        }
    }

#pragma unroll
    for (int rp = 0; rp < 4; rp++) {
#pragma unroll
        for (int h = 0; h < 2; h++) {
            int row = bm + ((rp & 2) ? tm1 : tm0) + (rp & 1) * 2 + h;
            if (row >= M) continue;
            int orow = row;
            if (EPI == 1 || EPI == 2) orow = row + (row / 3150) * 50 + 50;
#pragma unroll
            for (int j = 0; j < 8; j++) {
                unsigned long long u = acc2[rp][j];
                float v = h ? __uint_as_float((unsigned)(u >> 32))
                            : __uint_as_float((unsigned)(u & 0xffffffffull));
                int col = bn + ((j < 4) ? (tn0 + j) : (tn1 + j - 4));
                if (EPI == 0) {
                    C[(size_t)row * 512 + col] = v + bias[col];
                } else if (EPI == 1) {
                    C[(size_t)orow * 512 + col] =
                        res[(size_t)orow * 512 + col] + fmaxf(v + bias[col], 0.f);
                } else if (EPI == 2) {
                    C[(size_t)orow * 512 + col] += fmaxf(v + bias[col], 0.f);
                } else {
                    C[(size_t)row * 512 + col] =
                        res[(size_t)row * 512 + col] + fmaxf(v, 0.f);
                }
            }
        }
    }
}

// ---------------- fused spatial attention per (b,t) tile ----------------
// smem layout (floats): sx[50*516] | se[1536] | ss[50*52] | qn2[50] d0[50] d1[50] d2[50] en2[4] rs[50]
#define SX_STRIDE 516
#define SMEM_SPATIAL_FLOATS (50*516 + 1536 + 50*52 + 50*4 + 4 + 50)
#define SMEM_SPATIAL_BYTES  (SMEM_SPATIAL_FLOATS * 4)

__global__ void spatial_kernel(const float* __restrict__ x,
                               const float* __restrict__ edge,
                               const float* __restrict__ lng,
                               const float* __restrict__ lnb,
                               float* __restrict__ sp,
                               float* __restrict__ attn_out)
{
    extern __shared__ float sm[];
    float* sx  = sm;
    float* se  = sx + 50 * SX_STRIDE;
    float* ss  = se + 1536;
    float* qn2 = ss + 50 * 52;
    float* d0  = qn2 + 50;
    float* d1  = d0 + 50;
    float* d2  = d1 + 50;
    float* en2 = d2 + 50;
    float* rsv = en2 + 4;

    const int bt   = blockIdx.x;
    const int tid  = threadIdx.x;
    const int lane = tid & 31;
    const int w    = tid >> 5;
    const float* xg = x + (size_t)bt * 25600;

    for (int idx = tid; idx < 25600; idx += 256) {
        int i = idx >> 9, k = idx & 511;
        sx[i * SX_STRIDE + k] = xg[idx];
    }
    for (int idx = tid; idx < 1536; idx += 256) se[idx] = edge[idx];
    __syncthreads();

    // edge norms (warps 0..2) + per-row stats (all warps)
    if (w < 3) {
        float s = 0.f;
        for (int k = lane; k < 512; k += 32) { float e = se[w * 512 + k]; s += e * e; }
        s = warp_sum(s);
        if (lane == 0) en2[w] = s;
    }
    for (int i = w; i < 50; i += 8) {
        float sxx = 0.f, s0 = 0.f, s1 = 0.f, s2 = 0.f;
        for (int k = lane; k < 512; k += 32) {
            float v = sx[i * SX_STRIDE + k];
            sxx += v * v;
            s0 += v * se[k];
            s1 += v * se[512 + k];
            s2 += v * se[1024 + k];
        }
        sxx = warp_sum(sxx); s0 = warp_sum(s0); s1 = warp_sum(s1); s2 = warp_sum(s2);
        if (lane == 0) { qn2[i] = sxx; d0[i] = s0; d1[i] = s1; d2[i] = s2; }
    }
    __syncthreads();

    // G = X X^T  (4x4 strided register tile per thread)
    {
        int ty = tid >> 4, tx = tid & 15;
        const float* ap[4]; const float* bp[4];
#pragma unroll
        for (int u = 0; u < 4; u++) {
            int ri = ty + 16 * u; if (ri > 49) ri = 49;
            int rj = tx + 16 * u; if (rj > 49) rj = 49;
            ap[u] = sx + ri * SX_STRIDE;
            bp[u] = sx + rj * SX_STRIDE;
        }
        float acc[4][4];
#pragma unroll
        for (int i = 0; i < 4; i++)
#pragma unroll
            for (int j = 0; j < 4; j++) acc[i][j] = 0.f;
#pragma unroll 4
        for (int k = 0; k < 512; k++) {
            float a[4], b[4];
#pragma unroll
            for (int u = 0; u < 4; u++) { a[u] = ap[u][k]; b[u] = bp[u][k]; }
#pragma unroll
            for (int i = 0; i < 4; i++)
#pragma unroll
                for (int j = 0; j < 4; j++) acc[i][j] += a[i] * b[j];
        }
#pragma unroll
        for (int i = 0; i < 4; i++) {
            int gi = ty + 16 * i; if (gi >= 50) break;
#pragma unroll
            for (int j = 0; j < 4; j++) {
                int gj = tx + 16 * j;
                if (gj < 50) ss[gi * 52 + gj] = acc[i][j];
            }
        }
    }
    __syncthreads();

    // masked softmax per row (warp per row)
    for (int i = w; i < 50; i += 8) {
        float qi = fmaxf(sqrtf(qn2[i]), 1e-12f);
        float sv[2];
#pragma unroll
        for (int c = 0; c < 2; c++) {
            int j = lane + 32 * c;
            float s = -1e30f;
            if (j < 50) {
                if (j == i) {
                    s = NEGV;
                } else if (j == 49) {
                    float kn = fmaxf(sqrtf(qn2[49] + 2.f * d2[49] + en2[2]), 1e-12f);
                    s = (ss[i * 52 + 49] + d2[i]) / (qi * kn);
                } else if (i == 49) {
                    float kn = fmaxf(sqrtf(qn2[j] + 2.f * d1[j] + en2[1]), 1e-12f);
                    s = (ss[i * 52 + j] + d1[49]) / (qi * kn);
                } else {
                    int qr = i / 7, qc = i - qr * 7;
                    int kr = j / 7, kc = j - kr * 7;
                    int r0 = max(qr - 1, 0);
                    int c0 = min(max(qc - 1, 0), 4);
                    bool allow = (kr >= r0) && (kr <= r0 + 2) && (kc >= c0) && (kc <= c0 + 2);
                    if (allow) {
                        float kn = fmaxf(sqrtf(qn2[j] + 2.f * d0[j] + en2[0]), 1e-12f);
                        s = (ss[i * 52 + j] + d0[i]) / (qi * kn);
                    } else {
                        s = NEGV;
                    }
                }
            }
            sv[c] = s;
        }
        float m = warp_max(fmaxf(sv[0], sv[1]));
        float e0v = expf(sv[0] - m);
        float e1v = expf(sv[1] - m);
        if (lane + 32 >= 50) e1v = 0.f;
        float sum = warp_sum(e0v + e1v);
        float p0 = e0v / sum, p1 = e1v / sum;
        float rpart = ((lane < 49) ? p0 : 0.f) + ((lane + 32 < 49) ? p1 : 0.f);
        rpart = warp_sum(rpart);
        if (lane == 0) rsv[i] = rpart;
        if (lane < 50) {
            ss[i * 52 + lane] = p0;
            if (attn_out) attn_out[(size_t)bt * 2500 + i * 50 + lane] = p0;
        }
        if (lane + 32 < 50) {
            ss[i * 52 + lane + 32] = p1;
            if (attn_out) attn_out[(size_t)bt * 2500 + i * 50 + lane + 32] = p1;
        }
    }
    __syncthreads();

    // aggregation (2 rows / warp pass) + residual + LN + relu
    for (int pp = w; pp < 25; pp += 8) {
        int i0 = 2 * pp, i1 = 2 * pp + 1;
        float v0[16], v1[16];
#pragma unroll
        for (int m = 0; m < 16; m++) { v0[m] = 0.f; v1[m] = 0.f; }
        for (int j = 0; j < 50; j++) {
            float a0 = ss[i0 * 52 + j];
            float a1 = ss[i1 * 52 + j];
            const float* xr = sx + j * SX_STRIDE;
#pragma unroll
            for (int m = 0; m < 16; m++) {
                float xv = xr[lane + 32 * m];
                v0[m] += a0 * xv;
                v1[m] += a1 * xv;
            }
        }
#pragma unroll
        for (int which = 0; which < 2; which++) {
            int i = which ? i1 : i0;
            float* v = which ? v1 : v0;
            float rs = rsv[i];
            float a49 = ss[i * 52 + 49];
            const float* esel = (i < 49) ? se : (se + 512);
            float s = 0.f, s2 = 0.f;
#pragma unroll
            for (int m = 0; m < 16; m++) {
                int h = lane + 32 * m;
                float t = v[m] + rs * esel[h] + a49 * se[1024 + h] + sx[i * SX_STRIDE + h];
                v[m] = t;
                s += t; s2 += t * t;
            }
            s = warp_sum(s); s2 = warp_sum(s2);
            float mean = s * (1.f / 512.f);
            float var = s2 * (1.f / 512.f) - mean * mean;
            float rstd = rsqrtf(var + 1e-5f);
#pragma unroll
            for (int m = 0; m < 16; m++) {
                int h = lane + 32 * m;
                float y = (v[m] - mean) * rstd * lng[h] + lnb[h];
                sp[(size_t)bt * 25600 + i * 512 + h] = fmaxf(y, 0.f);
            }
        }
    }
}

// ---------------- temporal cosine ----------------
__global__ void cos_kernel(const float* __restrict__ sp, float* __restrict__ cosv,
                           float* __restrict__ cos_out)
{
    int r = blockIdx.x * 8 + (threadIdx.x >> 5);
    if (r >= 50400) return;
    int lane = threadIdx.x & 31;
    int b = r / 3150, rem = r - b * 3150;
    int tm = rem / 50, i = rem - tm * 50;
    const float* pa = sp + (size_t)((b * 64 + tm + 1) * 50 + i) * 512;
    const float* pb = sp + (size_t)((b * 64 + tm) * 50 + i) * 512;
    float dt = 0.f, na = 0.f, nb = 0.f;
    for (int k = lane; k < 512; k += 32) {
        float av = pa[k], bv = pb[k];
        dt += av * bv; na += av * av; nb += bv * bv;
    }
    dt = warp_sum(dt); na = warp_sum(na); nb = warp_sum(nb);
    if (lane == 0) {
        float c = dt / (fmaxf(sqrtf(na), 1e-8f) * fmaxf(sqrtf(nb), 1e-8f));
        cosv[r] = c;
        if (cos_out) cos_out[r] = c;
    }
}

// ---------------- layernorm of out_node (t==0 rows come from spatial) ----------------
__global__ void ln_kernel(const float* __restrict__ sp, const float* __restrict__ u,
                          const float* __restrict__ g, const float* __restrict__ b,
                          float* __restrict__ y)
{
    int r = blockIdx.x * 8 + (threadIdx.x >> 5);
    if (r >= 51200) return;
    int lane = threadIdx.x & 31;
    int t = (r / 50) & 63;
    const float* src = (t == 0) ? (sp + (size_t)r * 512) : (u + (size_t)r * 512);
    float v[16];
    float s = 0.f, s2 = 0.f;
#pragma unroll
    for (int m = 0; m < 16; m++) {
        float xv = src[lane + 32 * m];
        v[m] = xv; s += xv; s2 += xv * xv;
    }
    s = warp_sum(s); s2 = warp_sum(s2);
    float mean = s * (1.f / 512.f);
    float var = s2 * (1.f / 512.f) - mean * mean;
    float rstd = rsqrtf(var + 1e-5f);
#pragma unroll
    for (int m = 0; m < 16; m++) {
        int h = lane + 32 * m;
        y[(size_t)r * 512 + h] = (v[m] - mean) * rstd * g[h] + b[h];
    }
}

// ---------------- launch ----------------
extern "C" void kernel_launch(void* const* d_in, const int* in_sizes, int n_in,
                              void* d_out, int out_size)
{
    const float* vis   = (const float*)d_in[0];
    const float* aud   = (const float*)d_in[1];
    const float* in_W  = (const float*)d_in[2];
    const float* in_b  = (const float*)d_in[3];
    const float* out_W = (const float*)d_in[4];
    const float* out_b = (const float*)d_in[5];
    const float* L[2][8];
    for (int l = 0; l < 2; l++)
        for (int p = 0; p < 8; p++)
            L[l][p] = (const float*)d_in[6 + l * 8 + p];
    // per layer: 0 edge, 1 ln_g, 2 ln_b, 3 Wc, 4 bc, 5 Ws, 6 bs, 7 Wo

    float *px, *psp, *pu, *pcos;
    cudaGetSymbolAddress((void**)&px,   g_x);
    cudaGetSymbolAddress((void**)&psp,  g_sp);
    cudaGetSymbolAddress((void**)&pu,   g_u);
    cudaGetSymbolAddress((void**)&pcos, g_cs);

    float* out      = (float*)d_out;
    float* attn_out = out + 26214400;     // [16,64,50,50]
    float* cos_out  = out + 26214400 + 2560000;  // [16,63,50,1]

    cudaFuncSetAttribute(spatial_kernel,
                         cudaFuncAttributeMaxDynamicSharedMemorySize,
                         SMEM_SPATIAL_BYTES);

    dim3 g400(4, 400), g394(4, 394);

    // input projection: node = concat(visual, audio) @ in_W^T + in_b
    gemm512<1, 0><<<g400, 256>>>(nullptr, in_W, in_b, px, 51200,
                                 nullptr, nullptr, vis, aud);

    for (int l = 0; l < 2; l++) {
        bool last = (l == 1);
        spatial_kernel<<<1024, 256, SMEM_SPATIAL_BYTES>>>(
            px, L[l][0], L[l][1], L[l][2], psp, last ? attn_out : nullptr);
        cos_kernel<<<6300, 256>>>(psp, pcos, last ? cos_out : nullptr);
        // tc: g_u[cur] = cur + relu((cos*prev) @ Wc^T + bc)
        gemm512<2, 1><<<g394, 256>>>(psp, L[l][3], L[l][4], pu, 50400,
                                     pcos, psp, nullptr, nullptr);
        // ts: g_u[cur] += relu((cur*(1-cos)) @ Ws^T + bs)
        gemm512<3, 2><<<g394, 256>>>(psp, L[l][5], L[l][6], pu, 50400,
                                     pcos, nullptr, nullptr, nullptr);
        // layernorm(out_node) -> g_u (t==0 rows sourced from spatial)
        ln_kernel<<<6400, 256>>>(psp, pu, L[l][1], L[l][2], pu);
        // node = node + relu(LN @ Wo^T)   (in-place residual on g_x)
        gemm512<0, 3><<<g400, 256>>>(pu, L[l][7], nullptr, px, 51200,
                                     nullptr, px, nullptr, nullptr);
    }

    // final projection -> out
    gemm512<0, 0><<<g400, 256>>>(px, out_W, out_b, out, 51200,
                                 nullptr, nullptr, nullptr, nullptr);
}